// round 7
// baseline (speedup 1.0000x reference)
#include <cuda_runtime.h>
#include <cuda_fp16.h>
#include <cstdint>

// Problem constants
#define K_TOTAL 4096
#define N_TOTAL 11008
#define M_TOTAL 8192
#define NGROUPS 704512

// Scratch (static device globals)
__device__ __half g_W[(size_t)N_TOTAL * K_TOTAL];   // dequantized fp16, [out][in] K-major
__device__ __half g_x[(size_t)M_TOTAL * K_TOTAL];   // fp16 activations

// ---------------------------------------------------------------------------
// Kernel 1: dequantize packed 4-bit weights -> fp16. Four packed bytes/thread.
// ---------------------------------------------------------------------------
__global__ void dequant_w_kernel(const int4* __restrict__ Wq,
                                 const float4* __restrict__ scale,
                                 const float4* __restrict__ zero) {
    const int total = 32 * NGROUPS;
    int i = blockIdx.x * blockDim.x + threadIdx.x;   // quad index
    int base = i * 4;
    if (base >= total) return;
    int g4 = base % NGROUPS;
    int4 q = Wq[i];
    float4 s = scale[g4 >> 2];
    float4 z = zero[g4 >> 2];

    float h0 = ((float)((q.x >> 4) & 0xF) - z.x) * s.x;
    float l0 = ((float)(q.x & 0xF)        - z.x) * s.x;
    float h1 = ((float)((q.y >> 4) & 0xF) - z.y) * s.y;
    float l1 = ((float)(q.y & 0xF)        - z.y) * s.y;
    float h2 = ((float)((q.z >> 4) & 0xF) - z.z) * s.z;
    float l2 = ((float)(q.z & 0xF)        - z.z) * s.z;
    float h3 = ((float)((q.w >> 4) & 0xF) - z.w) * s.w;
    float l3 = ((float)(q.w & 0xF)        - z.w) * s.w;

    __half2 hA = __floats2half2_rn(h0, h1), hB = __floats2half2_rn(h2, h3);
    __half2 lA = __floats2half2_rn(l0, l1), lB = __floats2half2_rn(l2, l3);
    uint2 hs, ls;
    hs.x = *reinterpret_cast<uint32_t*>(&hA); hs.y = *reinterpret_cast<uint32_t*>(&hB);
    ls.x = *reinterpret_cast<uint32_t*>(&lA); ls.y = *reinterpret_cast<uint32_t*>(&lB);
    *reinterpret_cast<uint2*>(g_W + base)         = hs;
    *reinterpret_cast<uint2*>(g_W + base + total) = ls;
}

// ---------------------------------------------------------------------------
// Kernel 2: convert x fp32 -> fp16 (RNE). 8 elements/thread, 16B store.
// ---------------------------------------------------------------------------
__global__ void convx_kernel(const float4* __restrict__ x, int n8) {
    int i = blockIdx.x * blockDim.x + threadIdx.x;
    if (i >= n8) return;
    float4 v0 = x[2 * i];
    float4 v1 = x[2 * i + 1];
    __half2 a = __floats2half2_rn(v0.x, v0.y);
    __half2 b = __floats2half2_rn(v0.z, v0.w);
    __half2 c = __floats2half2_rn(v1.x, v1.y);
    __half2 d = __floats2half2_rn(v1.z, v1.w);
    uint4 o;
    o.x = *reinterpret_cast<uint32_t*>(&a);
    o.y = *reinterpret_cast<uint32_t*>(&b);
    o.z = *reinterpret_cast<uint32_t*>(&c);
    o.w = *reinterpret_cast<uint32_t*>(&d);
    reinterpret_cast<uint4*>(g_x)[i] = o;
}

// ---------------------------------------------------------------------------
// Kernel 3: fp16 tensor-core GEMM (mma.sync m16n8k16, fp32 accum).
// Block tile 128x128x64, 8 warps (2Mx4N, warp tile 64x32), 3-stage cp.async
// pipeline (96KB), 2 CTAs/SM. cp.async interleaved into the MMA stream AND
// fragment double-buffering across ks sub-steps (LDSM(ks+1) before MMA(ks)).
// ---------------------------------------------------------------------------
#define BK 64
#define STAGE_BYTES 32768            // A 16KB + B 16KB
#define NSTAGE 3
#define SMEM_TOTAL (NSTAGE * STAGE_BYTES)   // 98304

#define CP_ASYNC16(dst, src) \
    asm volatile("cp.async.cg.shared.global [%0], [%1], 16;" :: "r"(dst), "l"(src))
#define CP_COMMIT() asm volatile("cp.async.commit_group;" ::: "memory")
#define CP_WAIT(n)  asm volatile("cp.async.wait_group %0;" :: "n"(n) : "memory")

#define LDSM_X4(r0, r1, r2, r3, a)                                            \
    asm volatile("ldmatrix.sync.aligned.m8n8.x4.shared.b16 {%0,%1,%2,%3}, [%4];" \
                 : "=r"(r0), "=r"(r1), "=r"(r2), "=r"(r3) : "r"(a))

__global__ void __launch_bounds__(256, 2)
gemm_fp16_kernel(const float* __restrict__ bias, float* __restrict__ C) {
    extern __shared__ char smem[];
    uint32_t sbase;
    asm("{ .reg .u64 t; cvta.to.shared.u64 t, %1; cvt.u32.u64 %0, t; }"
        : "=r"(sbase) : "l"(smem));

    const int tid  = threadIdx.x;
    const int lane = tid & 31;
    const int warp = tid >> 5;
    const int wm   = warp & 1;      // 2 warps along M (64 rows each)
    const int wn   = warp >> 1;     // 4 warps along N (32 cols each)
    const int gID  = lane >> 2;
    const int t4   = lane & 3;

    // CTA swizzle: stripes of 16 M-tiles keep B panels L2-resident.
    const int tiles_n = N_TOTAL / 128;   // 86
    const int GRP = 16;
    int gid = blockIdx.x;
    int stripe = gid / (GRP * tiles_n);
    int rem = gid - stripe * (GRP * tiles_n);
    int tm = stripe * GRP + (rem % GRP);
    int tn = rem / GRP;
    const int m0 = tm * 128;
    const int n0 = tn * 128;

    const __half* Ag = g_x + (size_t)m0 * K_TOTAL;
    const __half* Bg = g_W + (size_t)n0 * K_TOTAL;

    float acc[4][4][4];
#pragma unroll
    for (int i = 0; i < 4; i++)
#pragma unroll
        for (int j = 0; j < 4; j++)
#pragma unroll
            for (int k = 0; k < 4; k++) acc[i][j][k] = 0.f;

    // Per-thread cp.async addressing constants
    const int crow = tid >> 3;           // 0..31
    const int ccc  = tid & 7;            // chunk
    const uint32_t cdst_off = (uint32_t)crow * 128 + (uint32_t)((ccc ^ (crow & 7)) << 4);

    auto issueA = [&](int kt, int stage) {
        int kbase = kt * BK;
        uint32_t stg = sbase + stage * STAGE_BYTES;
#pragma unroll
        for (int t = 0; t < 4; t++) {            // A: 128 rows x 8 chunks
            uint32_t dst = stg + t * 4096 + cdst_off;
            const __half* src = Ag + (size_t)(t * 32 + crow) * K_TOTAL + kbase + ccc * 8;
            CP_ASYNC16(dst, src);
        }
    };
    auto issueB = [&](int kt, int stage) {
        int kbase = kt * BK;
        uint32_t stg = sbase + stage * STAGE_BYTES + 16384;
#pragma unroll
        for (int t = 0; t < 4; t++) {            // B: 128 rows x 8 chunks
            uint32_t dst = stg + t * 4096 + cdst_off;
            const __half* src = Bg + (size_t)(t * 32 + crow) * K_TOTAL + kbase + ccc * 8;
            CP_ASYNC16(dst, src);
        }
    };

    // ldmatrix per-thread row/chunk decomposition
    const int arow = (lane & 7) + ((lane >> 3) & 1) * 8;   // 0..15
    const int akp  = lane >> 4;                            // 0/1 (k half)
    const int brow = (lane & 7) + (lane >> 4) * 8;         // 0..15
    const int bkp  = (lane >> 3) & 1;                      // 0/1 (k half)
    const int l7   = lane & 7;

    const uint32_t a_row_off = (uint32_t)(wm * 64 + arow) * 128;
    const uint32_t b_row_off = 16384u + (uint32_t)(wn * 32 + brow) * 128;

    // Double-buffered fragments
    uint32_t afr[2][4][4], bfr[2][2][4];

    auto ldfragA = [&](uint32_t stg, int ks, int buf) {
#pragma unroll
        for (int mt = 0; mt < 4; mt++) {
            uint32_t addr = stg + a_row_off + (uint32_t)(mt * 16) * 128 +
                            (uint32_t)(((2 * ks + akp) ^ l7) << 4);
            LDSM_X4(afr[buf][mt][0], afr[buf][mt][1],
                    afr[buf][mt][2], afr[buf][mt][3], addr);
        }
    };
    auto ldfragB = [&](uint32_t stg, int ks, int buf) {
#pragma unroll
        for (int p = 0; p < 2; p++) {
            uint32_t addr = stg + b_row_off + (uint32_t)(p * 16) * 128 +
                            (uint32_t)(((2 * ks + bkp) ^ l7) << 4);
            LDSM_X4(bfr[buf][p][0], bfr[buf][p][1],
                    bfr[buf][p][2], bfr[buf][p][3], addr);
        }
    };

    const int NK = K_TOTAL / BK;   // 64

    issueA(0, 0); issueB(0, 0); CP_COMMIT();
    issueA(1, 1); issueB(1, 1); CP_COMMIT();

    int stage = 0;
    for (int kt = 0; kt < NK; kt++) {
        CP_WAIT(1);
        __syncthreads();
        int s2 = stage + 2; if (s2 >= NSTAGE) s2 -= NSTAGE;
        const bool pf = (kt + 2 < NK);
        uint32_t stg = sbase + stage * STAGE_BYTES;

        // Prime ks=0 fragments (only exposed LDS latency in the stage).
        ldfragA(stg, 0, 0);
        ldfragB(stg, 0, 0);

#pragma unroll
        for (int ks = 0; ks < 4; ks++) {
            const int cur = ks & 1;
            const int nxt = cur ^ 1;
            // Prefetch next sub-step's fragments; latency hides under MMAs.
            if (ks < 3) { ldfragA(stg, ks + 1, nxt); ldfragB(stg, ks + 1, nxt); }
#pragma unroll
            for (int mt = 0; mt < 4; mt++)
#pragma unroll
                for (int nt = 0; nt < 4; nt++) {
                    uint32_t b0 = bfr[cur][nt >> 1][(nt & 1) * 2];
                    uint32_t b1 = bfr[cur][nt >> 1][(nt & 1) * 2 + 1];
                    asm volatile(
                        "mma.sync.aligned.m16n8k16.row.col.f32.f16.f16.f32 "
                        "{%0,%1,%2,%3}, {%4,%5,%6,%7}, {%8,%9}, {%0,%1,%2,%3};\n"
                        : "+f"(acc[mt][nt][0]), "+f"(acc[mt][nt][1]),
                          "+f"(acc[mt][nt][2]), "+f"(acc[mt][nt][3])
                        : "r"(afr[cur][mt][0]), "r"(afr[cur][mt][1]),
                          "r"(afr[cur][mt][2]), "r"(afr[cur][mt][3]),
                          "r"(b0), "r"(b1));
                }
            // Interleave next-stage global prefetch into the MMA stream.
            if (ks == 0 && pf) issueA(kt + 2, s2);
            if (ks == 1) { if (pf) issueB(kt + 2, s2); CP_COMMIT(); }
        }
        stage = (stage + 1 == NSTAGE) ? 0 : stage + 1;
    }

    // Epilogue: bias add + fp32 stores
    float2 bv[4];
#pragma unroll
    for (int nt = 0; nt < 4; nt++) {
        int col = n0 + wn * 32 + nt * 8 + t4 * 2;
        bv[nt] = *reinterpret_cast<const float2*>(bias + col);
    }
#pragma unroll
    for (int mt = 0; mt < 4; mt++) {
#pragma unroll
        for (int nt = 0; nt < 4; nt++) {
            int row0 = m0 + wm * 64 + mt * 16 + gID;
            int col  = n0 + wn * 32 + nt * 8 + t4 * 2;
            float2 v0 = make_float2(acc[mt][nt][0] + bv[nt].x, acc[mt][nt][1] + bv[nt].y);
            float2 v1 = make_float2(acc[mt][nt][2] + bv[nt].x, acc[mt][nt][3] + bv[nt].y);
            *reinterpret_cast<float2*>(C + (size_t)row0 * N_TOTAL + col)       = v0;
            *reinterpret_cast<float2*>(C + (size_t)(row0 + 8) * N_TOTAL + col) = v1;
        }
    }
}

// ---------------------------------------------------------------------------
// Launch. Inputs: x, W_q, scale, zero, bias. Output fp32.
// ---------------------------------------------------------------------------
extern "C" void kernel_launch(void* const* d_in, const int* in_sizes, int n_in,
                              void* d_out, int out_size) {
    const float* x     = (const float*)d_in[0];
    const int*   Wq    = (const int*)d_in[1];
    const float* scale = (const float*)d_in[2];
    const float* zero  = (const float*)d_in[3];
    const float* bias  = (const float*)d_in[4];
    float* out = (float*)d_out;

    {
        int quads = (32 * NGROUPS) / 4;
        int threads = 256;
        int blocks = (quads + threads - 1) / threads;
        dequant_w_kernel<<<blocks, threads>>>((const int4*)Wq,
                                              (const float4*)scale,
                                              (const float4*)zero);
    }
    {
        int n8 = (M_TOTAL * K_TOTAL) / 8;
        int threads = 256;
        int blocks = (n8 + threads - 1) / threads;
        convx_kernel<<<blocks, threads>>>((const float4*)x, n8);
    }
    {
        cudaFuncSetAttribute(gemm_fp16_kernel,
                             cudaFuncAttributeMaxDynamicSharedMemorySize, SMEM_TOTAL);
        int blocks = (M_TOTAL / 128) * (N_TOTAL / 128);   // 5504
        gemm_fp16_kernel<<<blocks, 256, SMEM_TOTAL>>>(bias, out);
    }
}

// round 8
// speedup vs baseline: 1.0650x; 1.0650x over previous
#include <cuda_runtime.h>
#include <cuda_fp16.h>
#include <cstdint>

// Problem constants
#define K_TOTAL 4096
#define N_TOTAL 11008
#define M_TOTAL 8192
#define NGROUPS 704512

// Scratch (static device globals)
__device__ __half g_W[(size_t)N_TOTAL * K_TOTAL];   // dequantized fp16, [out][in] K-major
__device__ __half g_x[(size_t)M_TOTAL * K_TOTAL];   // fp16 activations

// ---------------------------------------------------------------------------
// Kernel 1: dequantize packed 4-bit weights -> fp16. Four packed bytes/thread.
// ---------------------------------------------------------------------------
__global__ void dequant_w_kernel(const int4* __restrict__ Wq,
                                 const float4* __restrict__ scale,
                                 const float4* __restrict__ zero) {
    const int total = 32 * NGROUPS;
    int i = blockIdx.x * blockDim.x + threadIdx.x;   // quad index
    int base = i * 4;
    if (base >= total) return;
    int g4 = base % NGROUPS;
    int4 q = Wq[i];
    float4 s = scale[g4 >> 2];
    float4 z = zero[g4 >> 2];

    float h0 = ((float)((q.x >> 4) & 0xF) - z.x) * s.x;
    float l0 = ((float)(q.x & 0xF)        - z.x) * s.x;
    float h1 = ((float)((q.y >> 4) & 0xF) - z.y) * s.y;
    float l1 = ((float)(q.y & 0xF)        - z.y) * s.y;
    float h2 = ((float)((q.z >> 4) & 0xF) - z.z) * s.z;
    float l2 = ((float)(q.z & 0xF)        - z.z) * s.z;
    float h3 = ((float)((q.w >> 4) & 0xF) - z.w) * s.w;
    float l3 = ((float)(q.w & 0xF)        - z.w) * s.w;

    __half2 hA = __floats2half2_rn(h0, h1), hB = __floats2half2_rn(h2, h3);
    __half2 lA = __floats2half2_rn(l0, l1), lB = __floats2half2_rn(l2, l3);
    uint2 hs, ls;
    hs.x = *reinterpret_cast<uint32_t*>(&hA); hs.y = *reinterpret_cast<uint32_t*>(&hB);
    ls.x = *reinterpret_cast<uint32_t*>(&lA); ls.y = *reinterpret_cast<uint32_t*>(&lB);
    *reinterpret_cast<uint2*>(g_W + base)         = hs;
    *reinterpret_cast<uint2*>(g_W + base + total) = ls;
}

// ---------------------------------------------------------------------------
// Kernel 2: convert x fp32 -> fp16 (RNE). 8 elements/thread, 16B store.
// ---------------------------------------------------------------------------
__global__ void convx_kernel(const float4* __restrict__ x, int n8) {
    int i = blockIdx.x * blockDim.x + threadIdx.x;
    if (i >= n8) return;
    float4 v0 = x[2 * i];
    float4 v1 = x[2 * i + 1];
    __half2 a = __floats2half2_rn(v0.x, v0.y);
    __half2 b = __floats2half2_rn(v0.z, v0.w);
    __half2 c = __floats2half2_rn(v1.x, v1.y);
    __half2 d = __floats2half2_rn(v1.z, v1.w);
    uint4 o;
    o.x = *reinterpret_cast<uint32_t*>(&a);
    o.y = *reinterpret_cast<uint32_t*>(&b);
    o.z = *reinterpret_cast<uint32_t*>(&c);
    o.w = *reinterpret_cast<uint32_t*>(&d);
    reinterpret_cast<uint4*>(g_x)[i] = o;
}

// ---------------------------------------------------------------------------
// Kernel 3: fp16 tensor-core GEMM (mma.sync m16n8k16, fp32 accum).
// Block tile 128x128x64, 8 warps (2Mx4N, warp tile 64x32), 3-stage cp.async
// pipeline (96KB), 2 CTAs/SM. cp.async interleaved into the MMA stream.
// B fragments double-buffered across ks (fits the 128-reg budget; full
// double-buffering spilled in R7).
// ---------------------------------------------------------------------------
#define BK 64
#define STAGE_BYTES 32768            // A 16KB + B 16KB
#define NSTAGE 3
#define SMEM_TOTAL (NSTAGE * STAGE_BYTES)   // 98304

#define CP_ASYNC16(dst, src) \
    asm volatile("cp.async.cg.shared.global [%0], [%1], 16;" :: "r"(dst), "l"(src))
#define CP_COMMIT() asm volatile("cp.async.commit_group;" ::: "memory")
#define CP_WAIT(n)  asm volatile("cp.async.wait_group %0;" :: "n"(n) : "memory")

#define LDSM_X4(r0, r1, r2, r3, a)                                            \
    asm volatile("ldmatrix.sync.aligned.m8n8.x4.shared.b16 {%0,%1,%2,%3}, [%4];" \
                 : "=r"(r0), "=r"(r1), "=r"(r2), "=r"(r3) : "r"(a))

__global__ void __launch_bounds__(256, 2)
gemm_fp16_kernel(const float* __restrict__ bias, float* __restrict__ C) {
    extern __shared__ char smem[];
    uint32_t sbase;
    asm("{ .reg .u64 t; cvta.to.shared.u64 t, %1; cvt.u32.u64 %0, t; }"
        : "=r"(sbase) : "l"(smem));

    const int tid  = threadIdx.x;
    const int lane = tid & 31;
    const int warp = tid >> 5;
    const int wm   = warp & 1;      // 2 warps along M (64 rows each)
    const int wn   = warp >> 1;     // 4 warps along N (32 cols each)
    const int gID  = lane >> 2;
    const int t4   = lane & 3;

    // CTA swizzle: stripes of 16 M-tiles keep B panels L2-resident.
    const int tiles_n = N_TOTAL / 128;   // 86
    const int GRP = 16;
    int gid = blockIdx.x;
    int stripe = gid / (GRP * tiles_n);
    int rem = gid - stripe * (GRP * tiles_n);
    int tm = stripe * GRP + (rem % GRP);
    int tn = rem / GRP;
    const int m0 = tm * 128;
    const int n0 = tn * 128;

    const __half* Ag = g_x + (size_t)m0 * K_TOTAL;
    const __half* Bg = g_W + (size_t)n0 * K_TOTAL;

    float acc[4][4][4];
#pragma unroll
    for (int i = 0; i < 4; i++)
#pragma unroll
        for (int j = 0; j < 4; j++)
#pragma unroll
            for (int k = 0; k < 4; k++) acc[i][j][k] = 0.f;

    // Per-thread cp.async addressing constants
    const int crow = tid >> 3;           // 0..31
    const int ccc  = tid & 7;            // chunk
    const uint32_t cdst_off = (uint32_t)crow * 128 + (uint32_t)((ccc ^ (crow & 7)) << 4);

    auto issueA = [&](int kt, int stage) {
        int kbase = kt * BK;
        uint32_t stg = sbase + stage * STAGE_BYTES;
#pragma unroll
        for (int t = 0; t < 4; t++) {            // A: 128 rows x 8 chunks
            uint32_t dst = stg + t * 4096 + cdst_off;
            const __half* src = Ag + (size_t)(t * 32 + crow) * K_TOTAL + kbase + ccc * 8;
            CP_ASYNC16(dst, src);
        }
    };
    auto issueB = [&](int kt, int stage) {
        int kbase = kt * BK;
        uint32_t stg = sbase + stage * STAGE_BYTES + 16384;
#pragma unroll
        for (int t = 0; t < 4; t++) {            // B: 128 rows x 8 chunks
            uint32_t dst = stg + t * 4096 + cdst_off;
            const __half* src = Bg + (size_t)(t * 32 + crow) * K_TOTAL + kbase + ccc * 8;
            CP_ASYNC16(dst, src);
        }
    };

    // ldmatrix per-thread row/chunk decomposition
    const int arow = (lane & 7) + ((lane >> 3) & 1) * 8;   // 0..15
    const int akp  = lane >> 4;                            // 0/1 (k half)
    const int brow = (lane & 7) + (lane >> 4) * 8;         // 0..15
    const int bkp  = (lane >> 3) & 1;                      // 0/1 (k half)
    const int l7   = lane & 7;

    const uint32_t a_row_off = (uint32_t)(wm * 64 + arow) * 128;
    const uint32_t b_row_off = 16384u + (uint32_t)(wn * 32 + brow) * 128;

    // A single-buffered, B double-buffered
    uint32_t afr[4][4], bfr[2][2][4];

    auto ldfragA = [&](uint32_t stg, int ks) {
#pragma unroll
        for (int mt = 0; mt < 4; mt++) {
            uint32_t addr = stg + a_row_off + (uint32_t)(mt * 16) * 128 +
                            (uint32_t)(((2 * ks + akp) ^ l7) << 4);
            LDSM_X4(afr[mt][0], afr[mt][1], afr[mt][2], afr[mt][3], addr);
        }
    };
    auto ldfragB = [&](uint32_t stg, int ks, int buf) {
#pragma unroll
        for (int p = 0; p < 2; p++) {
            uint32_t addr = stg + b_row_off + (uint32_t)(p * 16) * 128 +
                            (uint32_t)(((2 * ks + bkp) ^ l7) << 4);
            LDSM_X4(bfr[buf][p][0], bfr[buf][p][1],
                    bfr[buf][p][2], bfr[buf][p][3], addr);
        }
    };

    const int NK = K_TOTAL / BK;   // 64

    issueA(0, 0); issueB(0, 0); CP_COMMIT();
    issueA(1, 1); issueB(1, 1); CP_COMMIT();

    int stage = 0;
    for (int kt = 0; kt < NK; kt++) {
        CP_WAIT(1);
        __syncthreads();
        int s2 = stage + 2; if (s2 >= NSTAGE) s2 -= NSTAGE;
        const bool pf = (kt + 2 < NK);
        uint32_t stg = sbase + stage * STAGE_BYTES;

        // Prime B(ks=0) fragments.
        ldfragB(stg, 0, 0);

#pragma unroll
        for (int ks = 0; ks < 4; ks++) {
            const int cur = ks & 1;
            const int nxt = cur ^ 1;
            // A for this ks (partially exposed), then B for next ks (hidden).
            ldfragA(stg, ks);
            if (ks < 3) ldfragB(stg, ks + 1, nxt);
#pragma unroll
            for (int mt = 0; mt < 4; mt++)
#pragma unroll
                for (int nt = 0; nt < 4; nt++) {
                    uint32_t b0 = bfr[cur][nt >> 1][(nt & 1) * 2];
                    uint32_t b1 = bfr[cur][nt >> 1][(nt & 1) * 2 + 1];
                    asm volatile(
                        "mma.sync.aligned.m16n8k16.row.col.f32.f16.f16.f32 "
                        "{%0,%1,%2,%3}, {%4,%5,%6,%7}, {%8,%9}, {%0,%1,%2,%3};\n"
                        : "+f"(acc[mt][nt][0]), "+f"(acc[mt][nt][1]),
                          "+f"(acc[mt][nt][2]), "+f"(acc[mt][nt][3])
                        : "r"(afr[mt][0]), "r"(afr[mt][1]),
                          "r"(afr[mt][2]), "r"(afr[mt][3]),
                          "r"(b0), "r"(b1));
                }
            // Interleave next-stage global prefetch into the MMA stream.
            if (ks == 0 && pf) issueA(kt + 2, s2);
            if (ks == 1) { if (pf) issueB(kt + 2, s2); CP_COMMIT(); }
        }
        stage = (stage + 1 == NSTAGE) ? 0 : stage + 1;
    }

    // Epilogue: bias add + fp32 stores
    float2 bv[4];
#pragma unroll
    for (int nt = 0; nt < 4; nt++) {
        int col = n0 + wn * 32 + nt * 8 + t4 * 2;
        bv[nt] = *reinterpret_cast<const float2*>(bias + col);
    }
#pragma unroll
    for (int mt = 0; mt < 4; mt++) {
#pragma unroll
        for (int nt = 0; nt < 4; nt++) {
            int row0 = m0 + wm * 64 + mt * 16 + gID;
            int col  = n0 + wn * 32 + nt * 8 + t4 * 2;
            float2 v0 = make_float2(acc[mt][nt][0] + bv[nt].x, acc[mt][nt][1] + bv[nt].y);
            float2 v1 = make_float2(acc[mt][nt][2] + bv[nt].x, acc[mt][nt][3] + bv[nt].y);
            *reinterpret_cast<float2*>(C + (size_t)row0 * N_TOTAL + col)       = v0;
            *reinterpret_cast<float2*>(C + (size_t)(row0 + 8) * N_TOTAL + col) = v1;
        }
    }
}

// ---------------------------------------------------------------------------
// Launch. Inputs: x, W_q, scale, zero, bias. Output fp32.
// ---------------------------------------------------------------------------
extern "C" void kernel_launch(void* const* d_in, const int* in_sizes, int n_in,
                              void* d_out, int out_size) {
    const float* x     = (const float*)d_in[0];
    const int*   Wq    = (const int*)d_in[1];
    const float* scale = (const float*)d_in[2];
    const float* zero  = (const float*)d_in[3];
    const float* bias  = (const float*)d_in[4];
    float* out = (float*)d_out;

    {
        int quads = (32 * NGROUPS) / 4;
        int threads = 256;
        int blocks = (quads + threads - 1) / threads;
        dequant_w_kernel<<<blocks, threads>>>((const int4*)Wq,
                                              (const float4*)scale,
                                              (const float4*)zero);
    }
    {
        int n8 = (M_TOTAL * K_TOTAL) / 8;
        int threads = 256;
        int blocks = (n8 + threads - 1) / threads;
        convx_kernel<<<blocks, threads>>>((const float4*)x, n8);
    }
    {
        cudaFuncSetAttribute(gemm_fp16_kernel,
                             cudaFuncAttributeMaxDynamicSharedMemorySize, SMEM_TOTAL);
        int blocks = (M_TOTAL / 128) * (N_TOTAL / 128);   // 5504
        gemm_fp16_kernel<<<blocks, 256, SMEM_TOTAL>>>(bias, out);
    }
}